// round 16
// baseline (speedup 1.0000x reference)
#include <cuda_runtime.h>
#include <cuda_fp16.h>
#include <cstdint>

// InstantNGPMLP fused on mma.sync m16n8k16 (tcgen05 unavailable under the
// harness's compute_103 virtual arch).
// R16 vs R13 (77.9us best: M=32, banked b[8], 12 warps/SM)
//     vs R15 (82.7us: per-j loads regressed -> banking is load-ahead ILP
//             that decouples the 29-cyc LDS latency from mma issue):
//   - KEEP R13's banked-b[8] compute structure + zero-C ks=0 mma.
//   - DROP only the raw-x prefetch (-32 regs -> ~132 live).
//   - CTA re-shape: THREADS=96, launch_bounds(96,5) -> reg cap 136,
//     15 warps/SM (R13 had 12). mma floor is 43us; R13 ran 55% duty.
//   - pure fp16 operands (rel_err 2.984e-4, 3.3x margin).

#define THREADS 96
#define WARPS 3
#define NROWS 1048576
#define WTILES (NROWS / 32)   // 32768 warp-tiles of 32 rows
#define GRID 740              // 5 CTAs/SM * 148

__device__ __forceinline__ void mma16816(float d[4], const uint32_t* a, uint32_t b0, uint32_t b1) {
    asm volatile(
        "mma.sync.aligned.m16n8k16.row.col.f32.f16.f16.f32 "
        "{%0,%1,%2,%3}, {%4,%5,%6,%7}, {%8,%9}, {%0,%1,%2,%3};"
        : "+f"(d[0]), "+f"(d[1]), "+f"(d[2]), "+f"(d[3])
        : "r"(a[0]), "r"(a[1]), "r"(a[2]), "r"(a[3]), "r"(b0), "r"(b1));
}
// Zero-C form: d = A*B (no accumulator pre-init).
__device__ __forceinline__ void mma16816_z(float d[4], const uint32_t* a, uint32_t b0, uint32_t b1) {
    asm volatile(
        "mma.sync.aligned.m16n8k16.row.col.f32.f16.f16.f32 "
        "{%0,%1,%2,%3}, {%4,%5,%6,%7}, {%8,%9}, {%10,%10,%10,%10};"
        : "=f"(d[0]), "=f"(d[1]), "=f"(d[2]), "=f"(d[3])
        : "r"(a[0]), "r"(a[1]), "r"(a[2]), "r"(a[3]), "r"(b0), "r"(b1), "f"(0.0f));
}

__device__ __forceinline__ uint32_t pack_h(float f0, float f1) {
    __half2 h = __floats2half2_rn(f0, f1);
    return *reinterpret_cast<uint32_t*>(&h);
}

// ---- smem: fp16 B fragments (~22KB) + biases ----
__shared__ uint2 sf1[512];    // L1: 2ks x 8nf x 32 lanes
__shared__ uint2 sf2[1024];   // L2: 4ks x 8nf x 32
__shared__ uint2 sf3[1024];   // L3
__shared__ uint2 sf4[256];    // L4: 4ks x 2nf x 32
__shared__ float sb1[64], sb2[64], sb3[64], sb4[16];

__device__ void stage(const float* __restrict__ W, int K, int N,
                      uint2* __restrict__ frag, int tid) {
    const int NF = N / 8, total = (K / 16) * NF * 32;
    for (int idx = tid; idx < total; idx += THREADS) {
        int lane = idx & 31, f = idx >> 5;
        int j = f % NF, ks = f / NF;
        int g = lane >> 2, t = lane & 3;
        int n = j * 8 + g;
        int k0 = ks * 16 + 2 * t;
        frag[idx] = make_uint2(pack_h(W[k0 * N + n],       W[(k0 + 1) * N + n]),
                               pack_h(W[(k0 + 8) * N + n], W[(k0 + 9) * N + n]));
    }
}

// Two-subtile layer, BANKED B loads (R13 pattern): per k-step load all NF
// frags first (load-ahead ILP), then 2*NF mma. ks=0 uses zero-C form.
template <int KS, int NF>
__device__ __forceinline__ void layer_mma2(float (&d0)[NF][4], float (&d1)[NF][4],
                                           const uint2* __restrict__ frag,
                                           const uint32_t* __restrict__ A0,
                                           const uint32_t* __restrict__ A1,
                                           int lane) {
#pragma unroll
    for (int ks = 0; ks < KS; ks++) {
        uint2 b[NF];
#pragma unroll
        for (int j = 0; j < NF; j++) b[j] = frag[(ks * NF + j) * 32 + lane];
        if (ks == 0) {
#pragma unroll
            for (int j = 0; j < NF; j++) mma16816_z(d0[j], &A0[0], b[j].x, b[j].y);
#pragma unroll
            for (int j = 0; j < NF; j++) mma16816_z(d1[j], &A1[0], b[j].x, b[j].y);
        } else {
#pragma unroll
            for (int j = 0; j < NF; j++) mma16816(d0[j], &A0[ks * 4], b[j].x, b[j].y);
#pragma unroll
            for (int j = 0; j < NF; j++) mma16816(d1[j], &A1[ks * 4], b[j].x, b[j].y);
        }
    }
}

// Epilogue: bias + relu + fp16 pack (one subtile).
__device__ __forceinline__ void epi_relu(const float (&d)[8][4],
                                         const float* __restrict__ bias, int lane,
                                         uint32_t* __restrict__ Ah) {
    int t = lane & 3;
#pragma unroll
    for (int ks = 0; ks < 4; ks++) {
#pragma unroll
        for (int h = 0; h < 2; h++) {
            int j = 2 * ks + h;
            float2 b = *(const float2*)&bias[j * 8 + 2 * t];
            float f0 = fmaxf(d[j][0] + b.x, 0.0f);
            float f1 = fmaxf(d[j][1] + b.y, 0.0f);
            float f2 = fmaxf(d[j][2] + b.x, 0.0f);
            float f3 = fmaxf(d[j][3] + b.y, 0.0f);
            Ah[ks * 4 + h * 2 + 0] = pack_h(f0, f1);
            Ah[ks * 4 + h * 2 + 1] = pack_h(f2, f3);
        }
    }
}

__global__ void __launch_bounds__(THREADS, 5)
mlp_hmma_kernel(const float* __restrict__ x,
                const float* __restrict__ Wi, const float* __restrict__ bi,
                const float* __restrict__ W1, const float* __restrict__ b1,
                const float* __restrict__ W2, const float* __restrict__ b2,
                const float* __restrict__ Wo, const float* __restrict__ bo,
                float* __restrict__ out) {
    const int tid = threadIdx.x;
    const int wid = tid >> 5;
    const int lane = tid & 31;
    const int g = lane >> 2, t = lane & 3;

    stage(Wi, 32, 64, sf1, tid);
    stage(W1, 64, 64, sf2, tid);
    stage(W2, 64, 64, sf3, tid);
    stage(Wo, 64, 16, sf4, tid);
    for (int i = tid; i < 64; i += THREADS) { sb1[i] = bi[i]; sb2[i] = b1[i]; sb3[i] = b2[i]; }
    if (tid < 16) sb4[tid] = bo[tid];
    __syncthreads();

    const int wstride = gridDim.x * WARPS;
    for (int wt = blockIdx.x * WARPS + wid; wt < WTILES; wt += wstride) {
        const size_t rowbase = (size_t)wt * 32;

        // ---- load x (32x32) -> fp16 A frags, 2 subtiles ----
        uint32_t A0[16], A1[16];
#pragma unroll
        for (int st = 0; st < 2; st++) {
            uint32_t* A = st ? A1 : A0;
            const float* xr0 = x + (rowbase + st * 16 + g) * 32;
            const float* xr8 = x + (rowbase + st * 16 + g + 8) * 32;
#pragma unroll
            for (int ks = 0; ks < 2; ks++) {
                float2 v0 = *(const float2*)&xr0[ks * 16 + 2 * t];
                float2 v1 = *(const float2*)&xr8[ks * 16 + 2 * t];
                float2 v2 = *(const float2*)&xr0[ks * 16 + 8 + 2 * t];
                float2 v3 = *(const float2*)&xr8[ks * 16 + 8 + 2 * t];
                A[ks * 4 + 0] = pack_h(v0.x, v0.y);
                A[ks * 4 + 1] = pack_h(v1.x, v1.y);
                A[ks * 4 + 2] = pack_h(v2.x, v2.y);
                A[ks * 4 + 3] = pack_h(v3.x, v3.y);
            }
        }

        float d0[8][4], d1[8][4];

        // ---- L1: 32 -> 64 ----
        layer_mma2<2, 8>(d0, d1, sf1, A0, A1, lane);
        epi_relu(d0, sb1, lane, A0);
        epi_relu(d1, sb1, lane, A1);

        // ---- L2: 64 -> 64 ----
        layer_mma2<4, 8>(d0, d1, sf2, A0, A1, lane);
        epi_relu(d0, sb2, lane, A0);
        epi_relu(d1, sb2, lane, A1);

        // ---- L3: 64 -> 64 ----
        layer_mma2<4, 8>(d0, d1, sf3, A0, A1, lane);
        epi_relu(d0, sb3, lane, A0);
        epi_relu(d1, sb3, lane, A1);

        // ---- L4: 64 -> 16 (no relu) ----
        float e0[2][4], e1[2][4];
        layer_mma2<4, 2>(e0, e1, sf4, A0, A1, lane);

        // ---- store both subtiles ----
#pragma unroll
        for (int mt = 0; mt < 2; mt++) {
            const float (&dd)[2][4] = mt ? e1 : e0;
            float* o0 = out + (rowbase + mt * 16 + g) * 16;
            float* o8 = out + (rowbase + mt * 16 + g + 8) * 16;
#pragma unroll
            for (int j = 0; j < 2; j++) {
                float2 b = *(const float2*)&sb4[j * 8 + 2 * t];
                *(float2*)&o0[j * 8 + 2 * t] = make_float2(dd[j][0] + b.x, dd[j][1] + b.y);
                *(float2*)&o8[j * 8 + 2 * t] = make_float2(dd[j][2] + b.x, dd[j][3] + b.y);
            }
        }
    }
}

extern "C" void kernel_launch(void* const* d_in, const int* in_sizes, int n_in,
                              void* d_out, int out_size) {
    (void)in_sizes; (void)n_in; (void)out_size;
    const float* x  = (const float*)d_in[0];
    const float* Wi = (const float*)d_in[1];
    const float* bi = (const float*)d_in[2];
    const float* W1 = (const float*)d_in[3];
    const float* b1 = (const float*)d_in[4];
    const float* W2 = (const float*)d_in[5];
    const float* b2 = (const float*)d_in[6];
    const float* Wo = (const float*)d_in[7];
    const float* bo = (const float*)d_in[8];
    float* out = (float*)d_out;

    mlp_hmma_kernel<<<GRID, THREADS>>>(x, Wi, bi, W1, b1, W2, b2, Wo, bo, out);
}

// round 17
// speedup vs baseline: 1.1764x; 1.1764x over previous
#include <cuda_runtime.h>
#include <cuda_fp16.h>
#include <cstdint>

// InstantNGPMLP fused on mma.sync m16n8k16 (tcgen05 unavailable under the
// harness's compute_103 virtual arch).
// R17 = R13 (77.9us best: M=32, banked b[8], x-prefetch, (128,3), 12 warps)
//       + two epilogue-only cuts (R14/R15/R16 proved every structural
//       perturbation of R13 regresses — so optimize within it):
//   - zero-C mma for ks=0: kills ~208 accumulator-init MOVs per tile.
//   - half2 epilogue: cvt f32x2->f16x2 then HADD2(bias)+HMAX2(relu);
//     6 ops/j vs 11. Bias pre-packed half2 in smem. Output layer keeps
//     fp32 bias-add.
//   - expected rel_err 3.5-4.5e-4 (one extra fp16 rounding on hidden
//     activations); revert epilogue if > 1e-3.

#define THREADS 128
#define WARPS 4
#define NROWS 1048576
#define WTILES (NROWS / 32)   // 32768 warp-tiles of 32 rows
#define GRID 444              // 3 CTAs/SM * 148

__device__ __forceinline__ void mma16816(float d[4], const uint32_t* a, uint32_t b0, uint32_t b1) {
    asm volatile(
        "mma.sync.aligned.m16n8k16.row.col.f32.f16.f16.f32 "
        "{%0,%1,%2,%3}, {%4,%5,%6,%7}, {%8,%9}, {%0,%1,%2,%3};"
        : "+f"(d[0]), "+f"(d[1]), "+f"(d[2]), "+f"(d[3])
        : "r"(a[0]), "r"(a[1]), "r"(a[2]), "r"(a[3]), "r"(b0), "r"(b1));
}
// Zero-C form: d = A*B (no accumulator pre-init).
__device__ __forceinline__ void mma16816_z(float d[4], const uint32_t* a, uint32_t b0, uint32_t b1) {
    asm volatile(
        "mma.sync.aligned.m16n8k16.row.col.f32.f16.f16.f32 "
        "{%0,%1,%2,%3}, {%4,%5,%6,%7}, {%8,%9}, {%10,%10,%10,%10};"
        : "=f"(d[0]), "=f"(d[1]), "=f"(d[2]), "=f"(d[3])
        : "r"(a[0]), "r"(a[1]), "r"(a[2]), "r"(a[3]), "r"(b0), "r"(b1), "f"(0.0f));
}

__device__ __forceinline__ uint32_t pack_h(float f0, float f1) {
    __half2 h = __floats2half2_rn(f0, f1);
    return *reinterpret_cast<uint32_t*>(&h);
}

// ---- smem: fp16 B fragments (~22KB) + biases ----
__shared__ uint2 sf1[512];    // L1: 2ks x 8nf x 32 lanes
__shared__ uint2 sf2[1024];   // L2: 4ks x 8nf x 32
__shared__ uint2 sf3[1024];   // L3
__shared__ uint2 sf4[256];    // L4: 4ks x 2nf x 32
__shared__ uint32_t sbh1[32], sbh2[32], sbh3[32];  // half2 bias per (j, t)
__shared__ float sb4[16];

__device__ void stage(const float* __restrict__ W, int K, int N,
                      uint2* __restrict__ frag, int tid) {
    const int NF = N / 8, total = (K / 16) * NF * 32;
    for (int idx = tid; idx < total; idx += THREADS) {
        int lane = idx & 31, f = idx >> 5;
        int j = f % NF, ks = f / NF;
        int g = lane >> 2, t = lane & 3;
        int n = j * 8 + g;
        int k0 = ks * 16 + 2 * t;
        frag[idx] = make_uint2(pack_h(W[k0 * N + n],       W[(k0 + 1) * N + n]),
                               pack_h(W[(k0 + 8) * N + n], W[(k0 + 9) * N + n]));
    }
}

// Two-subtile layer, banked B loads (R13 pattern); ks=0 uses zero-C form.
template <int KS, int NF>
__device__ __forceinline__ void layer_mma2(float (&d0)[NF][4], float (&d1)[NF][4],
                                           const uint2* __restrict__ frag,
                                           const uint32_t* __restrict__ A0,
                                           const uint32_t* __restrict__ A1,
                                           int lane) {
#pragma unroll
    for (int ks = 0; ks < KS; ks++) {
        uint2 b[NF];
#pragma unroll
        for (int j = 0; j < NF; j++) b[j] = frag[(ks * NF + j) * 32 + lane];
        if (ks == 0) {
#pragma unroll
            for (int j = 0; j < NF; j++) mma16816_z(d0[j], &A0[0], b[j].x, b[j].y);
#pragma unroll
            for (int j = 0; j < NF; j++) mma16816_z(d1[j], &A1[0], b[j].x, b[j].y);
        } else {
#pragma unroll
            for (int j = 0; j < NF; j++) mma16816(d0[j], &A0[ks * 4], b[j].x, b[j].y);
#pragma unroll
            for (int j = 0; j < NF; j++) mma16816(d1[j], &A1[ks * 4], b[j].x, b[j].y);
        }
    }
}

// half2 epilogue: cvt -> HADD2(bias) -> HMAX2(0) -> done (already packed).
__device__ __forceinline__ void epi_relu(const float (&d)[8][4],
                                         const uint32_t* __restrict__ biash, int lane,
                                         uint32_t* __restrict__ Ah) {
    const int t = lane & 3;
    const __half2 z = __floats2half2_rn(0.0f, 0.0f);
#pragma unroll
    for (int ks = 0; ks < 4; ks++) {
#pragma unroll
        for (int h = 0; h < 2; h++) {
            int j = 2 * ks + h;
            uint32_t bb = biash[j * 4 + t];
            __half2 b2 = *reinterpret_cast<__half2*>(&bb);
            __half2 p0 = __floats2half2_rn(d[j][0], d[j][1]);
            __half2 p1 = __floats2half2_rn(d[j][2], d[j][3]);
            p0 = __hmax2(__hadd2(p0, b2), z);
            p1 = __hmax2(__hadd2(p1, b2), z);
            Ah[ks * 4 + h * 2 + 0] = *reinterpret_cast<uint32_t*>(&p0);
            Ah[ks * 4 + h * 2 + 1] = *reinterpret_cast<uint32_t*>(&p1);
        }
    }
}

// Raw x loads for one 16-row subtile (8 float2 per thread).
__device__ __forceinline__ void load_raw(const float* __restrict__ x, size_t rowbase,
                                         int g, int t, float2* __restrict__ raw) {
    const float* xr0 = x + (rowbase + g) * 32;
    const float* xr8 = x + (rowbase + g + 8) * 32;
#pragma unroll
    for (int ks = 0; ks < 2; ks++) {
        raw[ks * 4 + 0] = *(const float2*)&xr0[ks * 16 + 2 * t];
        raw[ks * 4 + 1] = *(const float2*)&xr8[ks * 16 + 2 * t];
        raw[ks * 4 + 2] = *(const float2*)&xr0[ks * 16 + 8 + 2 * t];
        raw[ks * 4 + 3] = *(const float2*)&xr8[ks * 16 + 8 + 2 * t];
    }
}

__global__ void __launch_bounds__(THREADS, 3)
mlp_hmma_kernel(const float* __restrict__ x,
                const float* __restrict__ Wi, const float* __restrict__ bi,
                const float* __restrict__ W1, const float* __restrict__ b1,
                const float* __restrict__ W2, const float* __restrict__ b2,
                const float* __restrict__ Wo, const float* __restrict__ bo,
                float* __restrict__ out) {
    const int tid = threadIdx.x;
    const int wid = tid >> 5;
    const int lane = tid & 31;
    const int g = lane >> 2, t = lane & 3;

    stage(Wi, 32, 64, sf1, tid);
    stage(W1, 64, 64, sf2, tid);
    stage(W2, 64, 64, sf3, tid);
    stage(Wo, 64, 16, sf4, tid);
    // pack biases as half2 per (j, t): {b[8j+2t], b[8j+2t+1]}
    for (int i = tid; i < 32; i += THREADS) {
        int j = i >> 2, tt = i & 3;
        sbh1[i] = pack_h(bi[j * 8 + 2 * tt], bi[j * 8 + 2 * tt + 1]);
        sbh2[i] = pack_h(b1[j * 8 + 2 * tt], b1[j * 8 + 2 * tt + 1]);
        sbh3[i] = pack_h(b2[j * 8 + 2 * tt], b2[j * 8 + 2 * tt + 1]);
    }
    if (tid < 16) sb4[tid] = bo[tid];
    __syncthreads();

    const int wstride = gridDim.x * WARPS;
    int wt = blockIdx.x * WARPS + wid;

    // ---- prologue: raw x for first warp-tile (both subtiles) ----
    float2 raw[16];
    if (wt < WTILES) {
        load_raw(x, (size_t)wt * 32, g, t, raw);
        load_raw(x, (size_t)wt * 32 + 16, g, t, raw + 8);
    }

    for (; wt < WTILES; wt += wstride) {
        const size_t rowbase = (size_t)wt * 32;

        // ---- build fp16 A frags for both subtiles ----
        uint32_t A0[16], A1[16];
#pragma unroll
        for (int i = 0; i < 8; i++) A0[i] = pack_h(raw[i].x, raw[i].y);
#pragma unroll
        for (int i = 0; i < 8; i++) A1[i] = pack_h(raw[8 + i].x, raw[8 + i].y);

        // ---- prefetch next warp-tile's raw x ----
        int nwt = wt + wstride;
        if (nwt < WTILES) {
            load_raw(x, (size_t)nwt * 32, g, t, raw);
            load_raw(x, (size_t)nwt * 32 + 16, g, t, raw + 8);
        }

        float d0[8][4], d1[8][4];

        // ---- L1: 32 -> 64 ----
        layer_mma2<2, 8>(d0, d1, sf1, A0, A1, lane);
        epi_relu(d0, sbh1, lane, A0);
        epi_relu(d1, sbh1, lane, A1);

        // ---- L2: 64 -> 64 ----
        layer_mma2<4, 8>(d0, d1, sf2, A0, A1, lane);
        epi_relu(d0, sbh2, lane, A0);
        epi_relu(d1, sbh2, lane, A1);

        // ---- L3: 64 -> 64 ----
        layer_mma2<4, 8>(d0, d1, sf3, A0, A1, lane);
        epi_relu(d0, sbh3, lane, A0);
        epi_relu(d1, sbh3, lane, A1);

        // ---- L4: 64 -> 16 (no relu, fp32 bias on output path) ----
        float e0[2][4], e1[2][4];
        layer_mma2<4, 2>(e0, e1, sf4, A0, A1, lane);

        // ---- store both subtiles ----
#pragma unroll
        for (int mt = 0; mt < 2; mt++) {
            const float (&dd)[2][4] = mt ? e1 : e0;
            float* o0 = out + (rowbase + mt * 16 + g) * 16;
            float* o8 = out + (rowbase + mt * 16 + g + 8) * 16;
#pragma unroll
            for (int j = 0; j < 2; j++) {
                float2 b = *(const float2*)&sb4[j * 8 + 2 * t];
                *(float2*)&o0[j * 8 + 2 * t] = make_float2(dd[j][0] + b.x, dd[j][1] + b.y);
                *(float2*)&o8[j * 8 + 2 * t] = make_float2(dd[j][2] + b.x, dd[j][3] + b.y);
            }
        }
    }
}

extern "C" void kernel_launch(void* const* d_in, const int* in_sizes, int n_in,
                              void* d_out, int out_size) {
    (void)in_sizes; (void)n_in; (void)out_size;
    const float* x  = (const float*)d_in[0];
    const float* Wi = (const float*)d_in[1];
    const float* bi = (const float*)d_in[2];
    const float* W1 = (const float*)d_in[3];
    const float* b1 = (const float*)d_in[4];
    const float* W2 = (const float*)d_in[5];
    const float* b2 = (const float*)d_in[6];
    const float* Wo = (const float*)d_in[7];
    const float* bo = (const float*)d_in[8];
    float* out = (float*)d_out;

    mlp_hmma_kernel<<<GRID, THREADS>>>(x, Wi, bi, W1, b1, W2, b2, Wo, bo, out);
}